// round 3
// baseline (speedup 1.0000x reference)
#include <cuda_runtime.h>
#include <cuda_bf16.h>
#include <cstdint>

// Embedding gather: out[row, :] = table[token_ids[row], :]
//   table: [50257, 768] fp32 (d_in[1])
//   ids:   [16384]  int64 OR int32 (d_in[0]) -- width auto-detected
//   out:   [16384, 768] fp32
//
// Steady-state (graph replay loop): table rows L2-resident -> reads hit L2,
// the 48 MiB output write is the DRAM floor (~8us). Latency-bound, so: 8
// independent gathered LDG.128 per thread, 32-bit indexing, streaming stores.

#define VOCAB        50257
#define D_MODEL      768
#define VEC_PER_ROW  (D_MODEL / 4)   // 192 float4 per row
#define N_ROWS       16384
#define ROWS_PER_CTA 8

// Hot int32 token array (64 KiB), L2-resident across replays.
__device__ int g_tokens[N_ROWS];

// Width-detect + convert. All blocks read the SAME first 512 u64 words
// (4 KiB, L2 broadcast) so every block reaches the same verdict:
//   int64 layout: every u64 word is a token < VOCAB.
//   int32 layout: words pack two tokens; P(all 512 high halves zero)
//                 ~ (1/VOCAB)^512 ~= 0.
// Sample is in-bounds under both layouts (int32 buffer = 8192 u64 words).
__global__ void convert_ids_kernel(const unsigned long long* __restrict__ ids_u64) {
    bool is64 = true;
    #pragma unroll 4
    for (int i = threadIdx.x & 127; i < 512; i += 128) {
        if (ids_u64[i] >= (unsigned long long)VOCAB) is64 = false;
    }
    is64 = __all_sync(0xFFFFFFFFu, is64);

    const int idx = blockIdx.x * blockDim.x + threadIdx.x;
    if (idx < N_ROWS) {
        int tok;
        if (is64) tok = (int)((const long long*)ids_u64)[idx];
        else      tok = ((const int*)ids_u64)[idx];
        g_tokens[idx] = tok;
    }
}

// 8 rows per CTA, 192 threads; each thread: 8 block-uniform token loads
// (one round-trip), 8 independent gathered LDG.128 (4 KiB outstanding per
// warp), then 8 streaming STG.128. All indexing 32-bit.
__global__ __launch_bounds__(VEC_PER_ROW)
void embedding_gather_kernel(const float4* __restrict__ table,
                             float4* __restrict__ out) {
    const int row0 = blockIdx.x * ROWS_PER_CTA;
    const int t = threadIdx.x;

    int off[ROWS_PER_CTA];
    #pragma unroll
    for (int j = 0; j < ROWS_PER_CTA; j++)
        off[j] = g_tokens[row0 + j] * VEC_PER_ROW + t;   // uniform + t

    float4 v[ROWS_PER_CTA];
    #pragma unroll
    for (int j = 0; j < ROWS_PER_CTA; j++)
        v[j] = __ldg(table + off[j]);

    float4* dst = out + row0 * VEC_PER_ROW + t;
    #pragma unroll
    for (int j = 0; j < ROWS_PER_CTA; j++)
        __stcs(dst + j * VEC_PER_ROW, v[j]);
}

extern "C" void kernel_launch(void* const* d_in, const int* in_sizes, int n_in,
                              void* d_out, int out_size) {
    const void*   ids   = d_in[0];
    const float4* table = (const float4*)d_in[1];
    float4*       out   = (float4*)d_out;

    convert_ids_kernel<<<N_ROWS / 256, 256>>>((const unsigned long long*)ids);
    embedding_gather_kernel<<<N_ROWS / ROWS_PER_CTA, VEC_PER_ROW>>>(table, out);
}